// round 2
// baseline (speedup 1.0000x reference)
#include <cuda_runtime.h>
#include <cuda_bf16.h>
#include <cstdint>

// Problem constants
#define B_   32
#define L_   2048
#define D_   1024
#define NH_  16
#define DH_  64

// Scratch (device globals; no allocation)
__device__ float g_C [B_*NH_*D_];       // 2 MB  scaled combined query-key vectors
__device__ float g_cb[B_*NH_];          //       score bias (qs . bk) * 0.125
__device__ float g_S [B_*NH_*L_];       // 4 MB  raw scores
__device__ float g_M [4*B_*NH_*D_];     // 8 MB  weighted-k partial sums (4 l-splits)

// Packed dual-FMA (Blackwell f32x2 pipe)
__device__ __forceinline__ float2 ffma2(float2 a, float2 b, float2 c) {
    float2 d;
    asm("{\n\t"
        ".reg .b64 ra, rb, rc;\n\t"
        "mov.b64 ra, {%2,%3};\n\t"
        "mov.b64 rb, {%4,%5};\n\t"
        "mov.b64 rc, {%6,%7};\n\t"
        "fma.rn.f32x2 rc, ra, rb, rc;\n\t"
        "mov.b64 {%0,%1}, rc;\n\t"
        "}"
        : "=f"(d.x), "=f"(d.y)
        : "f"(a.x), "f"(a.y), "f"(b.x), "f"(b.y), "f"(c.x), "f"(c.y));
    return d;
}

// ---------------------------------------------------------------------------
// Kernel 1: qs = Wq_n q_b + bq ; c[b,n,:] = Wk_n^T qs * 0.125 ; cb = qs.bk*0.125
// grid 512 = (b,n), 128 threads
// ---------------------------------------------------------------------------
__global__ void k1_proj(const float* __restrict__ q,
                        const float* __restrict__ Wq,
                        const float* __restrict__ bq,
                        const float* __restrict__ Wk,
                        const float* __restrict__ bk) {
    int bid = blockIdx.x;
    int b = bid >> 4, n = bid & 15;
    __shared__ float qsh[D_];
    __shared__ float qs[DH_];
    int tid = threadIdx.x;
    int w = tid >> 5, lane = tid & 31;

    for (int i = tid; i < D_; i += 128) qsh[i] = q[b * D_ + i];
    __syncthreads();

    // warp w computes qs[d] for d in [w*16, w*16+16)
    for (int t = 0; t < 16; t++) {
        int d = w * 16 + t;
        int row = n * DH_ + d;
        const float* wr = Wq + (size_t)row * D_;
        float p = 0.f;
        #pragma unroll 4
        for (int i = lane; i < D_; i += 32) p += wr[i] * qsh[i];
        #pragma unroll
        for (int o = 16; o; o >>= 1) p += __shfl_xor_sync(0xFFFFFFFFu, p, o);
        if (lane == 0) qs[d] = p + bq[row];
    }
    __syncthreads();

    if (tid == 0) {
        float cb = 0.f;
        #pragma unroll
        for (int d = 0; d < DH_; d++) cb += qs[d] * bk[n * DH_ + d];
        g_cb[bid] = cb * 0.125f;
    }

    // C[bid][j] = sum_d qs[d] * Wk[n*64+d][j] * 0.125
    float acc[8];
    #pragma unroll
    for (int jj = 0; jj < 8; jj++) acc[jj] = 0.f;
    for (int d = 0; d < DH_; d++) {
        float qd = qs[d];
        const float* wr = Wk + (size_t)(n * DH_ + d) * D_ + tid;
        #pragma unroll
        for (int jj = 0; jj < 8; jj++) acc[jj] += qd * wr[jj * 128];
    }
    #pragma unroll
    for (int jj = 0; jj < 8; jj++)
        g_C[(size_t)bid * D_ + tid + jj * 128] = acc[jj] * 0.125f;
}

// ---------------------------------------------------------------------------
// Kernel 2: scores S[b,n,l] = C[b,n,:] . k[b,l,:] + cb[b,n]
// grid (8 l-tiles of 256, 32 b), 64 threads.
// Per thread: 8 n (as 4 f32x2 n-pairs) x 8 l (strided 32) = 64 outputs.
// Ks transposed [j=32][l=256] with pitch 33 (conflict-free scalar STS + LDS).
// ---------------------------------------------------------------------------
__global__ void __launch_bounds__(64) k2_scores(const float* __restrict__ k) {
    int lt = blockIdx.x;  // 0..7
    int b  = blockIdx.y;  // 0..31
    __shared__ float Ks[256 * 33];
    __shared__ float Cs[32 * 16];
    int tid = threadIdx.x;
    int ng = tid >> 5;    // n base = ng*8
    int lg = tid & 31;    // l = lg + 32*m

    float2 acc[4][8];
    #pragma unroll
    for (int p = 0; p < 4; p++)
        #pragma unroll
        for (int m = 0; m < 8; m++) acc[p][m] = make_float2(0.f, 0.f);

    const float* kb = k + ((size_t)b * L_ + (size_t)lt * 256) * D_;
    const float* Cb = g_C + (size_t)(b * NH_) * D_;

    for (int j0 = 0; j0 < D_; j0 += 32) {
        __syncthreads();
        // Cs[jp][nn]
        #pragma unroll
        for (int e = 0; e < 8; e++) {
            int f = tid + 64 * e;           // 0..511
            int jp = f >> 4, nn = f & 15;
            Cs[jp * 16 + nn] = Cb[(size_t)nn * D_ + j0 + jp];
        }
        // Ks[l][jj] transposed, pitch 33 -> conflict-free scalar STS
        #pragma unroll
        for (int r = 0; r < 32; r++) {
            int l = (tid >> 3) + 8 * r;     // 0..255
            int jj = (tid & 7) * 4;
            float4 v = *(const float4*)(kb + (size_t)l * D_ + j0 + jj);
            float* dst = &Ks[jj * 0];       // avoid unused warning trick
            dst = &Ks[l * 33 + jj];
            dst[0] = v.x; dst[1] = v.y; dst[2] = v.z; dst[3] = v.w;
        }
        __syncthreads();

        #pragma unroll 8
        for (int jp = 0; jp < 32; jp++) {
            float4 cA = *(const float4*)&Cs[jp * 16 + ng * 8];
            float4 cB = *(const float4*)&Cs[jp * 16 + ng * 8 + 4];
            float2 c0 = make_float2(cA.x, cA.y);
            float2 c1 = make_float2(cA.z, cA.w);
            float2 c2 = make_float2(cB.x, cB.y);
            float2 c3 = make_float2(cB.z, cB.w);
            const float* kcol = &Ks[lg * 33 + jp];
            #pragma unroll
            for (int m = 0; m < 8; m++) {
                float kv = kcol[m * 32 * 33];
                float2 ks = make_float2(kv, kv);
                acc[0][m] = ffma2(c0, ks, acc[0][m]);
                acc[1][m] = ffma2(c1, ks, acc[1][m]);
                acc[2][m] = ffma2(c2, ks, acc[2][m]);
                acc[3][m] = ffma2(c3, ks, acc[3][m]);
            }
        }
    }

    int col0 = lt * 256 + lg;
    #pragma unroll
    for (int p = 0; p < 4; p++) {
        int n0 = ng * 8 + 2 * p;
        float cb0 = g_cb[b * NH_ + n0];
        float cb1 = g_cb[b * NH_ + n0 + 1];
        float* r0 = g_S + (size_t)(b * NH_ + n0) * L_;
        float* r1 = r0 + L_;
        #pragma unroll
        for (int m = 0; m < 8; m++) {
            r0[col0 + 32 * m] = acc[p][m].x + cb0;
            r1[col0 + 32 * m] = acc[p][m].y + cb1;
        }
    }
}

// ---------------------------------------------------------------------------
// Kernel 3: softmax over l per (b,n); write attn_flat to d_out[32768 + ...]
// grid 512 = (b,n), 256 threads
// ---------------------------------------------------------------------------
__global__ void k3_softmax(float* __restrict__ dout) {
    int bid = blockIdx.x;
    int b = bid >> 4, n = bid & 15;
    const float* src = g_S + (size_t)bid * L_;
    float* dst = dout + (size_t)B_ * NH_ * DH_ + ((size_t)(n * B_ + b)) * L_;
    __shared__ float red[8];
    int tid = threadIdx.x;
    int w = tid >> 5, lane = tid & 31;

    float v[8];
    float mx = -1e30f;
    #pragma unroll
    for (int e = 0; e < 8; e++) {
        v[e] = src[tid + 256 * e];
        mx = fmaxf(mx, v[e]);
    }
    #pragma unroll
    for (int o = 16; o; o >>= 1) mx = fmaxf(mx, __shfl_xor_sync(0xFFFFFFFFu, mx, o));
    if (lane == 0) red[w] = mx;
    __syncthreads();
    float m_all = red[0];
    #pragma unroll
    for (int i = 1; i < 8; i++) m_all = fmaxf(m_all, red[i]);
    __syncthreads();

    float s = 0.f;
    #pragma unroll
    for (int e = 0; e < 8; e++) {
        v[e] = __expf(v[e] - m_all);
        s += v[e];
    }
    #pragma unroll
    for (int o = 16; o; o >>= 1) s += __shfl_xor_sync(0xFFFFFFFFu, s, o);
    if (lane == 0) red[w] = s;
    __syncthreads();
    float tot = 0.f;
    #pragma unroll
    for (int i = 0; i < 8; i++) tot += red[i];
    float inv = 1.0f / tot;
    #pragma unroll
    for (int e = 0; e < 8; e++) dst[tid + 256 * e] = v[e] * inv;
}

// ---------------------------------------------------------------------------
// Kernel 4: M_part[lp][b,n,j] = sum_{l in lp} attn[b,n,l] * k[b,l,j]
// grid (8 = 2 jt x 4 lp, 32 b), 128 threads.
// Per thread: 8 n x 8 j (4 f32x2 j-pairs) = 64 outputs.
// ---------------------------------------------------------------------------
__global__ void __launch_bounds__(128) k4_weighted(const float* __restrict__ k,
                                                   const float* __restrict__ dout) {
    int jt = blockIdx.x >> 2;     // 0..1
    int lp = blockIdx.x & 3;      // 0..3
    int b  = blockIdx.y;
    __shared__ float Ks[16 * 512];
    __shared__ float2 As2[16][16];
    int tid = threadIdx.x;
    int ng = tid >> 6;            // n base = ng*8
    int jg = tid & 63;            // j = jt*512 + jg*8 .. +8

    float2 acc[8][4];
    #pragma unroll
    for (int nn = 0; nn < 8; nn++)
        #pragma unroll
        for (int qq = 0; qq < 4; qq++) acc[nn][qq] = make_float2(0.f, 0.f);

    const float* attn = dout + (size_t)B_ * NH_ * DH_;
    const float* kb = k + ((size_t)b * L_) * D_ + jt * 512;

    int lend = lp * 512 + 512;
    for (int l0 = lp * 512; l0 < lend; l0 += 16) {
        __syncthreads();
        #pragma unroll
        for (int r = 0; r < 16; r++) {
            int f = tid + 128 * r;            // float4 index 0..2047
            int l = f >> 7, c = (f & 127) * 4;
            *(float4*)&Ks[l * 512 + c] =
                *(const float4*)(kb + (size_t)(l0 + l) * D_ + c);
        }
        #pragma unroll
        for (int e = 0; e < 2; e++) {
            int f = tid + 128 * e;            // 0..255
            int l = f >> 4, nn = f & 15;
            float a = attn[((size_t)(nn * B_ + b)) * L_ + l0 + l];
            As2[l][nn] = make_float2(a, a);
        }
        __syncthreads();

        #pragma unroll
        for (int li = 0; li < 16; li++) {
            const float4* ar = (const float4*)&As2[li][ng * 8];
            float4 a01 = ar[0], a23 = ar[1], a45 = ar[2], a67 = ar[3];
            float2 as[8];
            as[0] = make_float2(a01.x, a01.y);
            as[1] = make_float2(a01.z, a01.w);
            as[2] = make_float2(a23.x, a23.y);
            as[3] = make_float2(a23.z, a23.w);
            as[4] = make_float2(a45.x, a45.y);
            as[5] = make_float2(a45.z, a45.w);
            as[6] = make_float2(a67.x, a67.y);
            as[7] = make_float2(a67.z, a67.w);
            float4 k0 = *(const float4*)&Ks[li * 512 + jg * 8];
            float4 k1 = *(const float4*)&Ks[li * 512 + jg * 8 + 4];
            float2 kp[4];
            kp[0] = make_float2(k0.x, k0.y);
            kp[1] = make_float2(k0.z, k0.w);
            kp[2] = make_float2(k1.x, k1.y);
            kp[3] = make_float2(k1.z, k1.w);
            #pragma unroll
            for (int nn = 0; nn < 8; nn++)
                #pragma unroll
                for (int qq = 0; qq < 4; qq++)
                    acc[nn][qq] = ffma2(as[nn], kp[qq], acc[nn][qq]);
        }
    }

    // deterministic partial write: slot [lp]
    #pragma unroll
    for (int nn = 0; nn < 8; nn++) {
        int n = ng * 8 + nn;
        float* mrow = g_M + ((size_t)(lp * 512 + b * NH_ + n)) * D_ + jt * 512 + jg * 8;
        float4 o0 = make_float4(acc[nn][0].x, acc[nn][0].y, acc[nn][1].x, acc[nn][1].y);
        float4 o1 = make_float4(acc[nn][2].x, acc[nn][2].y, acc[nn][3].x, acc[nn][3].y);
        *(float4*)(mrow)     = o0;
        *(float4*)(mrow + 4) = o1;
    }
}

// ---------------------------------------------------------------------------
// Kernel 5: out[b, n*64+d] = Wv[n*64+d,:] . m[b,n,:] + bv   (sums 4 partials)
// grid 512 = (b,n), 128 threads
// ---------------------------------------------------------------------------
__global__ void k5_out(const float* __restrict__ Wv,
                       const float* __restrict__ bv,
                       float* __restrict__ dout) {
    int bid = blockIdx.x;
    int b = bid >> 4, n = bid & 15;
    __shared__ float Ms[D_];
    int tid = threadIdx.x;
    for (int i = tid; i < D_; i += 128) {
        float s = g_M[((size_t)(0 * 512 + bid)) * D_ + i]
                + g_M[((size_t)(1 * 512 + bid)) * D_ + i]
                + g_M[((size_t)(2 * 512 + bid)) * D_ + i]
                + g_M[((size_t)(3 * 512 + bid)) * D_ + i];
        Ms[i] = s;
    }
    __syncthreads();
    int w = tid >> 5, lane = tid & 31;
    for (int t = 0; t < 16; t++) {
        int d = w * 16 + t;
        int row = n * DH_ + d;
        const float* wr = Wv + (size_t)row * D_;
        float p = 0.f;
        #pragma unroll 4
        for (int i = lane; i < D_; i += 32) p += wr[i] * Ms[i];
        #pragma unroll
        for (int o = 16; o; o >>= 1) p += __shfl_xor_sync(0xFFFFFFFFu, p, o);
        if (lane == 0) dout[b * D_ + row] = bv[row] + p;
    }
}

// ---------------------------------------------------------------------------
extern "C" void kernel_launch(void* const* d_in, const int* in_sizes, int n_in,
                              void* d_out, int out_size) {
    const float* q  = (const float*)d_in[0];
    const float* k  = (const float*)d_in[1];
    const float* Wq = (const float*)d_in[2];
    const float* bq = (const float*)d_in[3];
    const float* Wk = (const float*)d_in[4];
    const float* bk = (const float*)d_in[5];
    const float* Wv = (const float*)d_in[6];
    const float* bv = (const float*)d_in[7];
    float* out = (float*)d_out;

    k1_proj   <<<512, 128>>>(q, Wq, bq, Wk, bk);
    k2_scores <<<dim3(8, 32), 64>>>(k);
    k3_softmax<<<512, 256>>>(out);
    k4_weighted<<<dim3(8, 32), 128>>>(k, out);
    k5_out    <<<512, 128>>>(Wv, bv, out);
}

// round 3
// speedup vs baseline: 1.1010x; 1.1010x over previous
#include <cuda_runtime.h>
#include <cuda_bf16.h>
#include <cstdint>

// Problem constants
#define B_   32
#define L_   2048
#define D_   1024
#define NH_  16
#define DH_  64

// Scratch (device globals; no allocation)
__device__ float g_C [B_*NH_*D_];          // 2 MB   combined query-key vectors (scaled by 1/8)
__device__ float g_S4[4][B_*NH_*L_];       // 16 MB  partial raw scores (4 j-chunks)
__device__ float g_M [16*B_*NH_*D_];       // 32 MB  weighted-k partial sums (16 l-splits)

// Packed dual-FMA (Blackwell f32x2 pipe)
__device__ __forceinline__ float2 ffma2(float2 a, float2 b, float2 c) {
    float2 d;
    asm("{\n\t"
        ".reg .b64 ra, rb, rc;\n\t"
        "mov.b64 ra, {%2,%3};\n\t"
        "mov.b64 rb, {%4,%5};\n\t"
        "mov.b64 rc, {%6,%7};\n\t"
        "fma.rn.f32x2 rc, ra, rb, rc;\n\t"
        "mov.b64 {%0,%1}, rc;\n\t"
        "}"
        : "=f"(d.x), "=f"(d.y)
        : "f"(a.x), "f"(a.y), "f"(b.x), "f"(b.y), "f"(c.x), "f"(c.y));
    return d;
}

// ---------------------------------------------------------------------------
// Kernel 1: qs = Wq_n q_b + bq ; C[b,n,:] = Wk_n^T qs * 0.125
// (score bias qs.bk is constant over l -> cancels in softmax -> dropped)
// grid 512 = (b,n), 128 threads
// ---------------------------------------------------------------------------
__global__ void k1_proj(const float* __restrict__ q,
                        const float* __restrict__ Wq,
                        const float* __restrict__ bq,
                        const float* __restrict__ Wk) {
    int bid = blockIdx.x;
    int b = bid >> 4, n = bid & 15;
    __shared__ float qsh[D_];
    __shared__ float qs[DH_];
    int tid = threadIdx.x;
    int w = tid >> 5, lane = tid & 31;

    for (int i = tid; i < D_; i += 128) qsh[i] = q[b * D_ + i];
    __syncthreads();

    for (int t = 0; t < 16; t++) {
        int d = w * 16 + t;
        int row = n * DH_ + d;
        const float* wr = Wq + (size_t)row * D_;
        float p = 0.f;
        #pragma unroll 4
        for (int i = lane; i < D_; i += 32) p += wr[i] * qsh[i];
        #pragma unroll
        for (int o = 16; o; o >>= 1) p += __shfl_xor_sync(0xFFFFFFFFu, p, o);
        if (lane == 0) qs[d] = p + bq[row];
    }
    __syncthreads();

    float acc[8];
    #pragma unroll
    for (int jj = 0; jj < 8; jj++) acc[jj] = 0.f;
    for (int d = 0; d < DH_; d++) {
        float qd = qs[d];
        const float* wr = Wk + (size_t)(n * DH_ + d) * D_ + tid;
        #pragma unroll
        for (int jj = 0; jj < 8; jj++) acc[jj] += qd * wr[jj * 128];
    }
    #pragma unroll
    for (int jj = 0; jj < 8; jj++)
        g_C[(size_t)bid * D_ + tid + jj * 128] = acc[jj] * 0.125f;
}

// ---------------------------------------------------------------------------
// Kernel 2: partial scores S4[js][b,n,l] = sum_{j in chunk js} C[b,n,j]*k[b,l,j]
// grid (lt=4, js=4, b=32) = 512 blocks, 128 threads.
// Block tile: 16 n x 512 l over a 256-j chunk. Per thread: 8n (4 f32x2) x 8l.
// Ks[l][jp] pitch 17 (conflict-free scalar LDS in compute).
// ---------------------------------------------------------------------------
__global__ void __launch_bounds__(128) k2_scores(const float* __restrict__ k) {
    int lt = blockIdx.x;            // 0..3  (512-l tile)
    int js = blockIdx.y;            // 0..3  (256-j chunk)
    int b  = blockIdx.z;
    __shared__ float Ks[512 * 17];  // 34.8 KB
    __shared__ float Cs[16 * 16];
    int tid = threadIdx.x;
    int ng = tid >> 6;              // 0..1 -> n base = ng*8
    int lg = tid & 63;              // l = lg + 64*m, m=0..7

    float2 acc[4][8];
    #pragma unroll
    for (int p = 0; p < 4; p++)
        #pragma unroll
        for (int m = 0; m < 8; m++) acc[p][m] = make_float2(0.f, 0.f);

    const float* kb = k + ((size_t)b * L_ + (size_t)lt * 512) * D_ + js * 256;
    const float* Cb = g_C + (size_t)(b * NH_) * D_ + js * 256;

    for (int j0 = 0; j0 < 256; j0 += 16) {
        __syncthreads();
        // Cs[jp][nn] : 256 floats
        {
            int i0 = tid * 2;
            #pragma unroll
            for (int e = 0; e < 2; e++) {
                int i = i0 + e;
                int jp = i >> 4, nn = i & 15;
                Cs[jp * 16 + nn] = Cb[(size_t)nn * D_ + j0 + jp];
            }
        }
        // Ks[l][jp], pitch 17: 512 l x 16 j
        #pragma unroll
        for (int r = 0; r < 16; r++) {
            int f = tid + 128 * r;          // 0..2047 float4 slots
            int l = f >> 2, c = (f & 3) * 4;
            float4 v = *(const float4*)(kb + (size_t)l * D_ + j0 + c);
            float* dst = &Ks[l * 17 + c];
            dst[0] = v.x; dst[1] = v.y; dst[2] = v.z; dst[3] = v.w;
        }
        __syncthreads();

        #pragma unroll
        for (int jp = 0; jp < 16; jp++) {
            float4 cA = *(const float4*)&Cs[jp * 16 + ng * 8];
            float4 cB = *(const float4*)&Cs[jp * 16 + ng * 8 + 4];
            float2 c0 = make_float2(cA.x, cA.y);
            float2 c1 = make_float2(cA.z, cA.w);
            float2 c2 = make_float2(cB.x, cB.y);
            float2 c3 = make_float2(cB.z, cB.w);
            #pragma unroll
            for (int m = 0; m < 8; m++) {
                float kv = Ks[(lg + 64 * m) * 17 + jp];
                float2 ks = make_float2(kv, kv);
                acc[0][m] = ffma2(c0, ks, acc[0][m]);
                acc[1][m] = ffma2(c1, ks, acc[1][m]);
                acc[2][m] = ffma2(c2, ks, acc[2][m]);
                acc[3][m] = ffma2(c3, ks, acc[3][m]);
            }
        }
    }

    int col0 = lt * 512 + lg;
    float* Sp = g_S4[js];
    #pragma unroll
    for (int p = 0; p < 4; p++) {
        int n0 = ng * 8 + 2 * p;
        float* r0 = Sp + (size_t)(b * NH_ + n0) * L_;
        float* r1 = r0 + L_;
        #pragma unroll
        for (int m = 0; m < 8; m++) {
            r0[col0 + 64 * m] = acc[p][m].x;
            r1[col0 + 64 * m] = acc[p][m].y;
        }
    }
}

// ---------------------------------------------------------------------------
// Kernel 3: sum 4 partials, softmax over l, write attn_flat to d_out
// grid 512 = (b,n), 256 threads
// ---------------------------------------------------------------------------
__global__ void k3_softmax(float* __restrict__ dout) {
    int bid = blockIdx.x;
    int b = bid >> 4, n = bid & 15;
    float* dst = dout + (size_t)B_ * NH_ * DH_ + ((size_t)(n * B_ + b)) * L_;
    __shared__ float red[8];
    int tid = threadIdx.x;
    int w = tid >> 5, lane = tid & 31;

    float v[8];
    float mx = -1e30f;
    #pragma unroll
    for (int e = 0; e < 8; e++) {
        size_t idx = (size_t)bid * L_ + tid + 256 * e;
        v[e] = g_S4[0][idx] + g_S4[1][idx] + g_S4[2][idx] + g_S4[3][idx];
        mx = fmaxf(mx, v[e]);
    }
    #pragma unroll
    for (int o = 16; o; o >>= 1) mx = fmaxf(mx, __shfl_xor_sync(0xFFFFFFFFu, mx, o));
    if (lane == 0) red[w] = mx;
    __syncthreads();
    float m_all = red[0];
    #pragma unroll
    for (int i = 1; i < 8; i++) m_all = fmaxf(m_all, red[i]);
    __syncthreads();

    float s = 0.f;
    #pragma unroll
    for (int e = 0; e < 8; e++) {
        v[e] = __expf(v[e] - m_all);
        s += v[e];
    }
    #pragma unroll
    for (int o = 16; o; o >>= 1) s += __shfl_xor_sync(0xFFFFFFFFu, s, o);
    if (lane == 0) red[w] = s;
    __syncthreads();
    float tot = 0.f;
    #pragma unroll
    for (int i = 0; i < 8; i++) tot += red[i];
    float inv = 1.0f / tot;
    #pragma unroll
    for (int e = 0; e < 8; e++) dst[tid + 256 * e] = v[e] * inv;
}

// ---------------------------------------------------------------------------
// Kernel 4: M[lp][b,n,j] = sum_{l in lp (128)} attn[b,n,l] * k[b,l,j]
// grid (jt*16+lp = 32, b = 32) = 1024 blocks, 128 threads.
// Per thread: 8 n x 8 j (two unit-strided float4 j-halves).
// ---------------------------------------------------------------------------
__global__ void __launch_bounds__(128) k4_weighted(const float* __restrict__ k,
                                                   const float* __restrict__ dout) {
    int jt = blockIdx.x >> 4;     // 0..1  (512-j half)
    int lp = blockIdx.x & 15;     // 0..15 (128-l split)
    int b  = blockIdx.y;
    __shared__ float Ks[16 * 512];     // 32 KB
    __shared__ float2 As2[16][16];
    int tid = threadIdx.x;
    int ng = tid >> 6;            // 0..1 -> n base = ng*8
    int jg = tid & 63;            // j halves at jg*4 and 256+jg*4

    float2 acc[8][4];
    #pragma unroll
    for (int nn = 0; nn < 8; nn++)
        #pragma unroll
        for (int qq = 0; qq < 4; qq++) acc[nn][qq] = make_float2(0.f, 0.f);

    const float* attn = dout + (size_t)B_ * NH_ * DH_;
    const float* kb = k + ((size_t)b * L_) * D_ + jt * 512;

    int lbeg = lp * 128, lend = lbeg + 128;
    for (int l0 = lbeg; l0 < lend; l0 += 16) {
        __syncthreads();
        #pragma unroll
        for (int r = 0; r < 16; r++) {
            int f = tid + 128 * r;            // float4 slot 0..2047
            int l = f >> 7, c = (f & 127) * 4;
            *(float4*)&Ks[l * 512 + c] =
                *(const float4*)(kb + (size_t)(l0 + l) * D_ + c);
        }
        #pragma unroll
        for (int e = 0; e < 2; e++) {
            int f = tid + 128 * e;            // 0..255
            int l = f >> 4, nn = f & 15;
            float a = attn[((size_t)(nn * B_ + b)) * L_ + l0 + l];
            As2[l][nn] = make_float2(a, a);
        }
        __syncthreads();

        #pragma unroll
        for (int li = 0; li < 16; li++) {
            const float4* ar = (const float4*)&As2[li][ng * 8];
            float4 a01 = ar[0], a23 = ar[1], a45 = ar[2], a67 = ar[3];
            float2 as[8];
            as[0] = make_float2(a01.x, a01.y);
            as[1] = make_float2(a01.z, a01.w);
            as[2] = make_float2(a23.x, a23.y);
            as[3] = make_float2(a23.z, a23.w);
            as[4] = make_float2(a45.x, a45.y);
            as[5] = make_float2(a45.z, a45.w);
            as[6] = make_float2(a67.x, a67.y);
            as[7] = make_float2(a67.z, a67.w);
            float4 k0 = *(const float4*)&Ks[li * 512 + jg * 4];
            float4 k1 = *(const float4*)&Ks[li * 512 + 256 + jg * 4];
            float2 kp[4];
            kp[0] = make_float2(k0.x, k0.y);
            kp[1] = make_float2(k0.z, k0.w);
            kp[2] = make_float2(k1.x, k1.y);
            kp[3] = make_float2(k1.z, k1.w);
            #pragma unroll
            for (int nn = 0; nn < 8; nn++)
                #pragma unroll
                for (int qq = 0; qq < 4; qq++)
                    acc[nn][qq] = ffma2(as[nn], kp[qq], acc[nn][qq]);
        }
    }

    #pragma unroll
    for (int nn = 0; nn < 8; nn++) {
        int n = ng * 8 + nn;
        float* mrow = g_M + ((size_t)(lp * 512 + b * NH_ + n)) * D_ + jt * 512;
        float4 o0 = make_float4(acc[nn][0].x, acc[nn][0].y, acc[nn][1].x, acc[nn][1].y);
        float4 o1 = make_float4(acc[nn][2].x, acc[nn][2].y, acc[nn][3].x, acc[nn][3].y);
        *(float4*)(mrow + jg * 4)       = o0;
        *(float4*)(mrow + 256 + jg * 4) = o1;
    }
}

// ---------------------------------------------------------------------------
// Kernel 5: out[b, n*64+d] = Wv[n*64+d,:] . m[b,n,:] + bv   (sums 16 partials)
// grid 512 = (b,n), 128 threads
// ---------------------------------------------------------------------------
__global__ void k5_out(const float* __restrict__ Wv,
                       const float* __restrict__ bv,
                       float* __restrict__ dout) {
    int bid = blockIdx.x;
    int b = bid >> 4, n = bid & 15;
    __shared__ float Ms[D_];
    int tid = threadIdx.x;
    for (int i = tid; i < D_; i += 128) {
        float s = 0.f;
        #pragma unroll
        for (int p = 0; p < 16; p++)
            s += g_M[((size_t)(p * 512 + bid)) * D_ + i];
        Ms[i] = s;
    }
    __syncthreads();
    int w = tid >> 5, lane = tid & 31;
    for (int t = 0; t < 16; t++) {
        int d = w * 16 + t;
        int row = n * DH_ + d;
        const float* wr = Wv + (size_t)row * D_;
        float p = 0.f;
        #pragma unroll 4
        for (int i = lane; i < D_; i += 32) p += wr[i] * Ms[i];
        #pragma unroll
        for (int o = 16; o; o >>= 1) p += __shfl_xor_sync(0xFFFFFFFFu, p, o);
        if (lane == 0) dout[b * D_ + row] = bv[row] + p;
    }
}

// ---------------------------------------------------------------------------
extern "C" void kernel_launch(void* const* d_in, const int* in_sizes, int n_in,
                              void* d_out, int out_size) {
    const float* q  = (const float*)d_in[0];
    const float* k  = (const float*)d_in[1];
    const float* Wq = (const float*)d_in[2];
    const float* bq = (const float*)d_in[3];
    const float* Wk = (const float*)d_in[4];
    const float* bk = (const float*)d_in[5];  (void)bk;
    const float* Wv = (const float*)d_in[6];
    const float* bv = (const float*)d_in[7];
    float* out = (float*)d_out;

    k1_proj   <<<512, 128>>>(q, Wq, bq, Wk);
    k2_scores <<<dim3(4, 4, 32), 128>>>(k);
    k3_softmax<<<512, 256>>>(out);
    k4_weighted<<<dim3(32, 32), 128>>>(k, out);
    k5_out    <<<512, 128>>>(Wv, bv, out);
}

// round 4
// speedup vs baseline: 1.2572x; 1.1419x over previous
#include <cuda_runtime.h>
#include <cuda_bf16.h>
#include <cstdint>

// Problem constants
#define B_   32
#define L_   2048
#define D_   1024
#define NH_  16
#define DH_  64

// Scratch (device globals; no allocation)
__device__ float g_C [B_*NH_*D_];          // 2 MB   combined query-key vectors (scaled by 1/8)
__device__ float g_S8[8][B_*NH_*L_];       // 32 MB  partial raw scores (8 j-chunks)
__device__ float g_M [16*B_*NH_*D_];       // 32 MB  weighted-k partial sums (16 l-splits)

// Packed dual-FMA (Blackwell f32x2 pipe)
__device__ __forceinline__ float2 ffma2(float2 a, float2 b, float2 c) {
    float2 d;
    asm("{\n\t"
        ".reg .b64 ra, rb, rc;\n\t"
        "mov.b64 ra, {%2,%3};\n\t"
        "mov.b64 rb, {%4,%5};\n\t"
        "mov.b64 rc, {%6,%7};\n\t"
        "fma.rn.f32x2 rc, ra, rb, rc;\n\t"
        "mov.b64 {%0,%1}, rc;\n\t"
        "}"
        : "=f"(d.x), "=f"(d.y)
        : "f"(a.x), "f"(a.y), "f"(b.x), "f"(b.y), "f"(c.x), "f"(c.y));
    return d;
}

// ---------------------------------------------------------------------------
// Kernel 1: qs = Wq_n q_b + bq ; C[b,n,:] = Wk_n^T qs * 0.125
// grid 512 = (b,n), 128 threads
// ---------------------------------------------------------------------------
__global__ void k1_proj(const float* __restrict__ q,
                        const float* __restrict__ Wq,
                        const float* __restrict__ bq,
                        const float* __restrict__ Wk) {
    int bid = blockIdx.x;
    int b = bid >> 4, n = bid & 15;
    __shared__ float qsh[D_];
    __shared__ float qs[DH_];
    int tid = threadIdx.x;
    int w = tid >> 5, lane = tid & 31;

    for (int i = tid; i < D_; i += 128) qsh[i] = q[b * D_ + i];
    __syncthreads();

    for (int t = 0; t < 16; t++) {
        int d = w * 16 + t;
        int row = n * DH_ + d;
        const float* wr = Wq + (size_t)row * D_;
        float p = 0.f;
        #pragma unroll 4
        for (int i = lane; i < D_; i += 32) p += wr[i] * qsh[i];
        #pragma unroll
        for (int o = 16; o; o >>= 1) p += __shfl_xor_sync(0xFFFFFFFFu, p, o);
        if (lane == 0) qs[d] = p + bq[row];
    }
    __syncthreads();

    float acc[8];
    #pragma unroll
    for (int jj = 0; jj < 8; jj++) acc[jj] = 0.f;
    for (int d = 0; d < DH_; d++) {
        float qd = qs[d];
        const float* wr = Wk + (size_t)(n * DH_ + d) * D_ + tid;
        #pragma unroll
        for (int jj = 0; jj < 8; jj++) acc[jj] += qd * wr[jj * 128];
    }
    #pragma unroll
    for (int jj = 0; jj < 8; jj++)
        g_C[(size_t)bid * D_ + tid + jj * 128] = acc[jj] * 0.125f;
}

// ---------------------------------------------------------------------------
// Kernel 2 (k4-mirror): partial scores over a 128-j chunk.
// S8[js][b,n,l] = sum_{j in chunk} C[b,n,j] * k[b,l,j]
// grid (lt=4, js=8, b=32) = 1024 blocks, 128 threads.
// Block tile 16n x 512l; per thread 8n x 8l (4 l-pair float2 accs).
// Streamed j staged TRANSPOSED: KsT[j][l] pitch 516; C staged as splat pairs.
// Inner loop identical in shape to k4: 4x LDS.128 bc + 2x LDS.128 + 32 ffma2.
// ---------------------------------------------------------------------------
__global__ void __launch_bounds__(128) k2_scores(const float* __restrict__ k) {
    int lt = blockIdx.x;            // 0..3  (512-l tile)
    int js = blockIdx.y;            // 0..7  (128-j chunk)
    int b  = blockIdx.z;
    __shared__ float  KsT[16 * 516];   // 33 KB  [j-in-step][l], pitch 516
    __shared__ float2 Cs2[16][18];     // splat pairs [j-in-step][n]
    int tid = threadIdx.x;
    int ng = tid >> 6;              // 0..1 -> n base = ng*8
    int lg = tid & 63;              // l sets: lg*4..+4 and 256+lg*4..+4

    float2 acc[8][4];
    #pragma unroll
    for (int nn = 0; nn < 8; nn++)
        #pragma unroll
        for (int lp = 0; lp < 4; lp++) acc[nn][lp] = make_float2(0.f, 0.f);

    const float* kb = k + ((size_t)b * L_ + (size_t)lt * 512) * D_ + js * 128;
    const float* Cb = g_C + (size_t)(b * NH_) * D_ + js * 128;

    for (int step = 0; step < 8; step++) {
        int j0 = step * 16;
        __syncthreads();
        // stage C splat pairs: 16 ji x 16 n
        #pragma unroll
        for (int e = 0; e < 2; e++) {
            int f = tid + 128 * e;          // 0..255
            int ji = f >> 4, nn = f & 15;
            float c = Cb[(size_t)nn * D_ + j0 + ji];
            Cs2[ji][nn] = make_float2(c, c);
        }
        // stage KsT transposed: 512 l x 16 j  (scalar STS, ~2-way conflicts)
        #pragma unroll
        for (int r = 0; r < 16; r++) {
            int f = tid + 128 * r;          // 0..2047 float4 slots
            int l = f >> 2, c = (f & 3) * 4;
            float4 v = *(const float4*)(kb + (size_t)l * D_ + j0 + c);
            KsT[(c + 0) * 516 + l] = v.x;
            KsT[(c + 1) * 516 + l] = v.y;
            KsT[(c + 2) * 516 + l] = v.z;
            KsT[(c + 3) * 516 + l] = v.w;
        }
        __syncthreads();

        #pragma unroll
        for (int ji = 0; ji < 16; ji++) {
            const float4* cr = (const float4*)&Cs2[ji][ng * 8];
            float4 cA = cr[0], cB = cr[1], cC = cr[2], cD = cr[3];
            float2 cs[8];
            cs[0] = make_float2(cA.x, cA.y);
            cs[1] = make_float2(cA.z, cA.w);
            cs[2] = make_float2(cB.x, cB.y);
            cs[3] = make_float2(cB.z, cB.w);
            cs[4] = make_float2(cC.x, cC.y);
            cs[5] = make_float2(cC.z, cC.w);
            cs[6] = make_float2(cD.x, cD.y);
            cs[7] = make_float2(cD.z, cD.w);
            float4 kA = *(const float4*)&KsT[ji * 516 + lg * 4];
            float4 kB = *(const float4*)&KsT[ji * 516 + 256 + lg * 4];
            float2 kp[4];
            kp[0] = make_float2(kA.x, kA.y);
            kp[1] = make_float2(kA.z, kA.w);
            kp[2] = make_float2(kB.x, kB.y);
            kp[3] = make_float2(kB.z, kB.w);
            #pragma unroll
            for (int nn = 0; nn < 8; nn++)
                #pragma unroll
                for (int lp = 0; lp < 4; lp++)
                    acc[nn][lp] = ffma2(cs[nn], kp[lp], acc[nn][lp]);
        }
    }

    float* Sp = g_S8[js];
    #pragma unroll
    for (int nn = 0; nn < 8; nn++) {
        int n = ng * 8 + nn;
        float* base = Sp + (size_t)(b * NH_ + n) * L_ + lt * 512;
        float4 o0 = make_float4(acc[nn][0].x, acc[nn][0].y, acc[nn][1].x, acc[nn][1].y);
        float4 o1 = make_float4(acc[nn][2].x, acc[nn][2].y, acc[nn][3].x, acc[nn][3].y);
        *(float4*)(base + lg * 4)       = o0;
        *(float4*)(base + 256 + lg * 4) = o1;
    }
}

// ---------------------------------------------------------------------------
// Kernel 3: sum 8 partials, softmax over l, write attn_flat to d_out
// grid 512 = (b,n), 256 threads
// ---------------------------------------------------------------------------
__global__ void k3_softmax(float* __restrict__ dout) {
    int bid = blockIdx.x;
    int b = bid >> 4, n = bid & 15;
    float* dst = dout + (size_t)B_ * NH_ * DH_ + ((size_t)(n * B_ + b)) * L_;
    __shared__ float red[8];
    int tid = threadIdx.x;
    int w = tid >> 5, lane = tid & 31;

    float v[8];
    float mx = -1e30f;
    #pragma unroll
    for (int e = 0; e < 8; e++) {
        size_t idx = (size_t)bid * L_ + tid + 256 * e;
        float s = 0.f;
        #pragma unroll
        for (int p = 0; p < 8; p++) s += g_S8[p][idx];
        v[e] = s;
        mx = fmaxf(mx, v[e]);
    }
    #pragma unroll
    for (int o = 16; o; o >>= 1) mx = fmaxf(mx, __shfl_xor_sync(0xFFFFFFFFu, mx, o));
    if (lane == 0) red[w] = mx;
    __syncthreads();
    float m_all = red[0];
    #pragma unroll
    for (int i = 1; i < 8; i++) m_all = fmaxf(m_all, red[i]);
    __syncthreads();

    float s = 0.f;
    #pragma unroll
    for (int e = 0; e < 8; e++) {
        v[e] = __expf(v[e] - m_all);
        s += v[e];
    }
    #pragma unroll
    for (int o = 16; o; o >>= 1) s += __shfl_xor_sync(0xFFFFFFFFu, s, o);
    if (lane == 0) red[w] = s;
    __syncthreads();
    float tot = 0.f;
    #pragma unroll
    for (int i = 0; i < 8; i++) tot += red[i];
    float inv = 1.0f / tot;
    #pragma unroll
    for (int e = 0; e < 8; e++) dst[tid + 256 * e] = v[e] * inv;
}

// ---------------------------------------------------------------------------
// Kernel 4: M[lp][b,n,j] = sum_{l in lp (128)} attn[b,n,l] * k[b,l,j]
// grid (jt*16+lp = 32, b = 32) = 1024 blocks, 128 threads.  (unchanged)
// ---------------------------------------------------------------------------
__global__ void __launch_bounds__(128) k4_weighted(const float* __restrict__ k,
                                                   const float* __restrict__ dout) {
    int jt = blockIdx.x >> 4;     // 0..1  (512-j half)
    int lp = blockIdx.x & 15;     // 0..15 (128-l split)
    int b  = blockIdx.y;
    __shared__ float Ks[16 * 512];     // 32 KB
    __shared__ float2 As2[16][16];
    int tid = threadIdx.x;
    int ng = tid >> 6;            // 0..1 -> n base = ng*8
    int jg = tid & 63;            // j halves at jg*4 and 256+jg*4

    float2 acc[8][4];
    #pragma unroll
    for (int nn = 0; nn < 8; nn++)
        #pragma unroll
        for (int qq = 0; qq < 4; qq++) acc[nn][qq] = make_float2(0.f, 0.f);

    const float* attn = dout + (size_t)B_ * NH_ * DH_;
    const float* kb = k + ((size_t)b * L_) * D_ + jt * 512;

    int lbeg = lp * 128, lend = lbeg + 128;
    for (int l0 = lbeg; l0 < lend; l0 += 16) {
        __syncthreads();
        #pragma unroll
        for (int r = 0; r < 16; r++) {
            int f = tid + 128 * r;            // float4 slot 0..2047
            int l = f >> 7, c = (f & 127) * 4;
            *(float4*)&Ks[l * 512 + c] =
                *(const float4*)(kb + (size_t)(l0 + l) * D_ + c);
        }
        #pragma unroll
        for (int e = 0; e < 2; e++) {
            int f = tid + 128 * e;            // 0..255
            int l = f >> 4, nn = f & 15;
            float a = attn[((size_t)(nn * B_ + b)) * L_ + l0 + l];
            As2[l][nn] = make_float2(a, a);
        }
        __syncthreads();

        #pragma unroll
        for (int li = 0; li < 16; li++) {
            const float4* ar = (const float4*)&As2[li][ng * 8];
            float4 a01 = ar[0], a23 = ar[1], a45 = ar[2], a67 = ar[3];
            float2 as[8];
            as[0] = make_float2(a01.x, a01.y);
            as[1] = make_float2(a01.z, a01.w);
            as[2] = make_float2(a23.x, a23.y);
            as[3] = make_float2(a23.z, a23.w);
            as[4] = make_float2(a45.x, a45.y);
            as[5] = make_float2(a45.z, a45.w);
            as[6] = make_float2(a67.x, a67.y);
            as[7] = make_float2(a67.z, a67.w);
            float4 k0 = *(const float4*)&Ks[li * 512 + jg * 4];
            float4 k1 = *(const float4*)&Ks[li * 512 + 256 + jg * 4];
            float2 kp[4];
            kp[0] = make_float2(k0.x, k0.y);
            kp[1] = make_float2(k0.z, k0.w);
            kp[2] = make_float2(k1.x, k1.y);
            kp[3] = make_float2(k1.z, k1.w);
            #pragma unroll
            for (int nn = 0; nn < 8; nn++)
                #pragma unroll
                for (int qq = 0; qq < 4; qq++)
                    acc[nn][qq] = ffma2(as[nn], kp[qq], acc[nn][qq]);
        }
    }

    #pragma unroll
    for (int nn = 0; nn < 8; nn++) {
        int n = ng * 8 + nn;
        float* mrow = g_M + ((size_t)(lp * 512 + b * NH_ + n)) * D_ + jt * 512;
        float4 o0 = make_float4(acc[nn][0].x, acc[nn][0].y, acc[nn][1].x, acc[nn][1].y);
        float4 o1 = make_float4(acc[nn][2].x, acc[nn][2].y, acc[nn][3].x, acc[nn][3].y);
        *(float4*)(mrow + jg * 4)       = o0;
        *(float4*)(mrow + 256 + jg * 4) = o1;
    }
}

// ---------------------------------------------------------------------------
// Kernel 5: out[b, n*64+d] = Wv[n*64+d,:] . m[b,n,:] + bv   (sums 16 partials)
// grid 512 = (b,n), 128 threads
// ---------------------------------------------------------------------------
__global__ void k5_out(const float* __restrict__ Wv,
                       const float* __restrict__ bv,
                       float* __restrict__ dout) {
    int bid = blockIdx.x;
    int b = bid >> 4, n = bid & 15;
    __shared__ float Ms[D_];
    int tid = threadIdx.x;
    for (int i = tid; i < D_; i += 128) {
        float s = 0.f;
        #pragma unroll
        for (int p = 0; p < 16; p++)
            s += g_M[((size_t)(p * 512 + bid)) * D_ + i];
        Ms[i] = s;
    }
    __syncthreads();
    int w = tid >> 5, lane = tid & 31;
    for (int t = 0; t < 16; t++) {
        int d = w * 16 + t;
        int row = n * DH_ + d;
        const float* wr = Wv + (size_t)row * D_;
        float p = 0.f;
        #pragma unroll 4
        for (int i = lane; i < D_; i += 32) p += wr[i] * Ms[i];
        #pragma unroll
        for (int o = 16; o; o >>= 1) p += __shfl_xor_sync(0xFFFFFFFFu, p, o);
        if (lane == 0) dout[b * D_ + row] = bv[row] + p;
    }
}

// ---------------------------------------------------------------------------
extern "C" void kernel_launch(void* const* d_in, const int* in_sizes, int n_in,
                              void* d_out, int out_size) {
    const float* q  = (const float*)d_in[0];
    const float* k  = (const float*)d_in[1];
    const float* Wq = (const float*)d_in[2];
    const float* bq = (const float*)d_in[3];
    const float* Wk = (const float*)d_in[4];
    const float* bk = (const float*)d_in[5];  (void)bk;
    const float* Wv = (const float*)d_in[6];
    const float* bv = (const float*)d_in[7];
    float* out = (float*)d_out;

    k1_proj   <<<512, 128>>>(q, Wq, bq, Wk);
    k2_scores <<<dim3(4, 8, 32), 128>>>(k);
    k3_softmax<<<512, 256>>>(out);
    k4_weighted<<<dim3(32, 32), 128>>>(k, out);
    k5_out    <<<512, 128>>>(Wv, bv, out);
}

// round 5
// speedup vs baseline: 1.6708x; 1.3290x over previous
#include <cuda_runtime.h>
#include <cuda_bf16.h>
#include <cstdint>

// Problem constants
#define B_   32
#define L_   2048
#define D_   1024
#define NH_  16
#define DH_  64

// Scratch (device globals; no allocation)
__device__ float g_qs[B_*NH_*DH_];         // 128 KB qs = Wq q + bq
__device__ float g_C [B_*NH_*D_];          // 2 MB   combined query-key vectors (scaled by 1/8)
__device__ float g_S8[8][B_*NH_*L_];       // 32 MB  partial raw scores (8 j-chunks)
__device__ float g_M [32*B_*NH_*D_];       // 64 MB  weighted-k partial sums (32 l-splits)
__device__ float g_m [B_*NH_*D_];          // 2 MB   reduced weighted-k sums

// Packed dual-FMA (Blackwell f32x2 pipe)
__device__ __forceinline__ float2 ffma2(float2 a, float2 b, float2 c) {
    float2 d;
    asm("{\n\t"
        ".reg .b64 ra, rb, rc;\n\t"
        "mov.b64 ra, {%2,%3};\n\t"
        "mov.b64 rb, {%4,%5};\n\t"
        "mov.b64 rc, {%6,%7};\n\t"
        "fma.rn.f32x2 rc, ra, rb, rc;\n\t"
        "mov.b64 {%0,%1}, rc;\n\t"
        "}"
        : "=f"(d.x), "=f"(d.y)
        : "f"(a.x), "f"(a.y), "f"(b.x), "f"(b.y), "f"(c.x), "f"(c.y));
    return d;
}

#define CP_ASYNC16(dst_u32, src_ptr) \
    asm volatile("cp.async.cg.shared.global [%0], [%1], 16;" \
                 :: "r"(dst_u32), "l"(src_ptr) : "memory")
#define CP_COMMIT() asm volatile("cp.async.commit_group;" ::: "memory")

// ---------------------------------------------------------------------------
// Kernel 1a: qs[b, row] = Wq[row,:] . q[b,:] + bq[row]
// grid (rb=8, b=32), 256 threads (8 warps x 16 rows each). Wq read ONCE.
// ---------------------------------------------------------------------------
__global__ void k1a_qs(const float* __restrict__ q,
                       const float* __restrict__ Wq,
                       const float* __restrict__ bq) {
    int rb = blockIdx.x, b = blockIdx.y;
    __shared__ float4 q4[D_ / 4];
    int tid = threadIdx.x;
    int w = tid >> 5, lane = tid & 31;

    for (int i = tid; i < D_ / 4; i += 256)
        q4[i] = ((const float4*)(q + (size_t)b * D_))[i];
    __syncthreads();

    for (int t = 0; t < 16; t++) {
        int row = rb * 128 + w * 16 + t;
        const float4* wr = (const float4*)(Wq + (size_t)row * D_);
        float p = 0.f;
        #pragma unroll
        for (int it = 0; it < 8; it++) {
            int idx = lane + 32 * it;
            float4 a = wr[idx], qv = q4[idx];
            p += a.x * qv.x + a.y * qv.y + a.z * qv.z + a.w * qv.w;
        }
        #pragma unroll
        for (int o = 16; o; o >>= 1) p += __shfl_xor_sync(0xFFFFFFFFu, p, o);
        if (lane == 0) g_qs[(size_t)b * D_ + row] = p + bq[row];
    }
}

// ---------------------------------------------------------------------------
// Kernel 1b: C[b,n,j] = 0.125 * sum_d qs[b, n*64+d] * Wk[n*64+d, j]
// grid (jt=8, n=16), 128 threads (thread = one j column). Wk read ONCE.
// ---------------------------------------------------------------------------
__global__ void k1b_C(const float* __restrict__ Wk) {
    int jt = blockIdx.x, n = blockIdx.y;
    __shared__ float Ws[DH_ * 128];   // 32 KB: Wk tile [d][j]
    __shared__ float Qs[B_ * DH_];    // 8 KB:  qs tile [b][d]
    int tid = threadIdx.x;

    #pragma unroll
    for (int r = 0; r < 16; r++) {
        int f = tid + 128 * r;        // 0..2047
        int b = f >> 6, d = f & 63;
        Qs[b * DH_ + d] = g_qs[(size_t)b * D_ + n * DH_ + d];
    }
    #pragma unroll
    for (int r = 0; r < 64; r++)
        Ws[r * 128 + tid] = Wk[(size_t)(n * DH_ + r) * D_ + jt * 128 + tid];
    __syncthreads();

    float acc[B_];
    #pragma unroll
    for (int b = 0; b < B_; b++) acc[b] = 0.f;
    for (int d = 0; d < DH_; d++) {
        float w = Ws[d * 128 + tid];
        #pragma unroll
        for (int b = 0; b < B_; b++) acc[b] += Qs[b * DH_ + d] * w;
    }
    #pragma unroll
    for (int b = 0; b < B_; b++)
        g_C[(size_t)(b * NH_ + n) * D_ + jt * 128 + tid] = acc[b] * 0.125f;
}

// ---------------------------------------------------------------------------
// Kernel 2: partial scores over a 128-j chunk (unchanged from R4).
// grid (lt=4, js=8, b=32) = 1024 blocks, 128 threads.
// ---------------------------------------------------------------------------
__global__ void __launch_bounds__(128) k2_scores(const float* __restrict__ k) {
    int lt = blockIdx.x;
    int js = blockIdx.y;
    int b  = blockIdx.z;
    __shared__ float  KsT[16 * 516];
    __shared__ float2 Cs2[16][18];
    int tid = threadIdx.x;
    int ng = tid >> 6;
    int lg = tid & 63;

    float2 acc[8][4];
    #pragma unroll
    for (int nn = 0; nn < 8; nn++)
        #pragma unroll
        for (int lp = 0; lp < 4; lp++) acc[nn][lp] = make_float2(0.f, 0.f);

    const float* kb = k + ((size_t)b * L_ + (size_t)lt * 512) * D_ + js * 128;
    const float* Cb = g_C + (size_t)(b * NH_) * D_ + js * 128;

    for (int step = 0; step < 8; step++) {
        int j0 = step * 16;
        __syncthreads();
        #pragma unroll
        for (int e = 0; e < 2; e++) {
            int f = tid + 128 * e;
            int ji = f >> 4, nn = f & 15;
            float c = Cb[(size_t)nn * D_ + j0 + ji];
            Cs2[ji][nn] = make_float2(c, c);
        }
        #pragma unroll
        for (int r = 0; r < 16; r++) {
            int f = tid + 128 * r;
            int l = f >> 2, c = (f & 3) * 4;
            float4 v = *(const float4*)(kb + (size_t)l * D_ + j0 + c);
            KsT[(c + 0) * 516 + l] = v.x;
            KsT[(c + 1) * 516 + l] = v.y;
            KsT[(c + 2) * 516 + l] = v.z;
            KsT[(c + 3) * 516 + l] = v.w;
        }
        __syncthreads();

        #pragma unroll
        for (int ji = 0; ji < 16; ji++) {
            const float4* cr = (const float4*)&Cs2[ji][ng * 8];
            float4 cA = cr[0], cB = cr[1], cC = cr[2], cD = cr[3];
            float2 cs[8];
            cs[0] = make_float2(cA.x, cA.y);
            cs[1] = make_float2(cA.z, cA.w);
            cs[2] = make_float2(cB.x, cB.y);
            cs[3] = make_float2(cB.z, cB.w);
            cs[4] = make_float2(cC.x, cC.y);
            cs[5] = make_float2(cC.z, cC.w);
            cs[6] = make_float2(cD.x, cD.y);
            cs[7] = make_float2(cD.z, cD.w);
            float4 kA = *(const float4*)&KsT[ji * 516 + lg * 4];
            float4 kB = *(const float4*)&KsT[ji * 516 + 256 + lg * 4];
            float2 kp[4];
            kp[0] = make_float2(kA.x, kA.y);
            kp[1] = make_float2(kA.z, kA.w);
            kp[2] = make_float2(kB.x, kB.y);
            kp[3] = make_float2(kB.z, kB.w);
            #pragma unroll
            for (int nn = 0; nn < 8; nn++)
                #pragma unroll
                for (int lp = 0; lp < 4; lp++)
                    acc[nn][lp] = ffma2(cs[nn], kp[lp], acc[nn][lp]);
        }
    }

    float* Sp = g_S8[js];
    #pragma unroll
    for (int nn = 0; nn < 8; nn++) {
        int n = ng * 8 + nn;
        float* base = Sp + (size_t)(b * NH_ + n) * L_ + lt * 512;
        float4 o0 = make_float4(acc[nn][0].x, acc[nn][0].y, acc[nn][1].x, acc[nn][1].y);
        float4 o1 = make_float4(acc[nn][2].x, acc[nn][2].y, acc[nn][3].x, acc[nn][3].y);
        *(float4*)(base + lg * 4)       = o0;
        *(float4*)(base + 256 + lg * 4) = o1;
    }
}

// ---------------------------------------------------------------------------
// Kernel 3: sum 8 partials, softmax over l, write attn_flat to d_out
// ---------------------------------------------------------------------------
__global__ void k3_softmax(float* __restrict__ dout) {
    int bid = blockIdx.x;
    int b = bid >> 4, n = bid & 15;
    float* dst = dout + (size_t)B_ * NH_ * DH_ + ((size_t)(n * B_ + b)) * L_;
    __shared__ float red[8];
    int tid = threadIdx.x;
    int w = tid >> 5, lane = tid & 31;

    float v[8];
    float mx = -1e30f;
    #pragma unroll
    for (int e = 0; e < 8; e++) {
        size_t idx = (size_t)bid * L_ + tid + 256 * e;
        float s = 0.f;
        #pragma unroll
        for (int p = 0; p < 8; p++) s += g_S8[p][idx];
        v[e] = s;
        mx = fmaxf(mx, v[e]);
    }
    #pragma unroll
    for (int o = 16; o; o >>= 1) mx = fmaxf(mx, __shfl_xor_sync(0xFFFFFFFFu, mx, o));
    if (lane == 0) red[w] = mx;
    __syncthreads();
    float m_all = red[0];
    #pragma unroll
    for (int i = 1; i < 8; i++) m_all = fmaxf(m_all, red[i]);
    __syncthreads();

    float s = 0.f;
    #pragma unroll
    for (int e = 0; e < 8; e++) {
        v[e] = __expf(v[e] - m_all);
        s += v[e];
    }
    #pragma unroll
    for (int o = 16; o; o >>= 1) s += __shfl_xor_sync(0xFFFFFFFFu, s, o);
    if (lane == 0) red[w] = s;
    __syncthreads();
    float tot = 0.f;
    #pragma unroll
    for (int i = 0; i < 8; i++) tot += red[i];
    float inv = 1.0f / tot;
    #pragma unroll
    for (int e = 0; e < 8; e++) dst[tid + 256 * e] = v[e] * inv;
}

// ---------------------------------------------------------------------------
// Kernel 4: M[lp][b,n,j] = sum_{l in lp (64)} attn[b,n,l] * k[b,l,j]
// grid (jt=2, lp=32, b=32) = 2048 blocks, 128 threads.
// cp.async double-buffered staging, 8-l chunks.
// ---------------------------------------------------------------------------
__global__ void __launch_bounds__(128) k4_weighted(const float* __restrict__ k,
                                                   const float* __restrict__ dout) {
    int jt = blockIdx.x;          // 0..1
    int lp = blockIdx.y;          // 0..31
    int b  = blockIdx.z;
    __shared__ float Ks[2][8 * 512];      // 2 x 16 KB
    __shared__ float2 As2[2][8][16];      // 2 x 1 KB
    int tid = threadIdx.x;
    int ng = tid >> 6;
    int jg = tid & 63;

    float2 acc[8][4];
    #pragma unroll
    for (int nn = 0; nn < 8; nn++)
        #pragma unroll
        for (int qq = 0; qq < 4; qq++) acc[nn][qq] = make_float2(0.f, 0.f);

    const float* attn = dout + (size_t)B_ * NH_ * DH_;
    const float* kb = k + ((size_t)b * L_) * D_ + jt * 512;
    int lbeg = lp * 64;

    // stage chunk (8 l) into buffer s
    auto stage = [&](int s, int l0) {
        #pragma unroll
        for (int r = 0; r < 8; r++) {
            int f = tid + 128 * r;            // float4 slot 0..1023
            int l = f >> 7, c = (f & 127) * 4;
            uint32_t dst = (uint32_t)__cvta_generic_to_shared(&Ks[s][l * 512 + c]);
            CP_ASYNC16(dst, kb + (size_t)(l0 + l) * D_ + c);
        }
        int l = tid >> 4, nn = tid & 15;      // 8 l x 16 n = 128
        float a = attn[((size_t)(nn * B_ + b)) * L_ + l0 + l];
        As2[s][l][nn] = make_float2(a, a);
    };

    stage(0, lbeg);
    CP_COMMIT();

    for (int c = 0; c < 8; c++) {
        if (c < 7) {
            stage((c + 1) & 1, lbeg + (c + 1) * 8);
            CP_COMMIT();
            asm volatile("cp.async.wait_group 1;" ::: "memory");
        } else {
            asm volatile("cp.async.wait_group 0;" ::: "memory");
        }
        __syncthreads();

        int buf = c & 1;
        #pragma unroll
        for (int li = 0; li < 8; li++) {
            const float4* ar = (const float4*)&As2[buf][li][ng * 8];
            float4 a01 = ar[0], a23 = ar[1], a45 = ar[2], a67 = ar[3];
            float2 as[8];
            as[0] = make_float2(a01.x, a01.y);
            as[1] = make_float2(a01.z, a01.w);
            as[2] = make_float2(a23.x, a23.y);
            as[3] = make_float2(a23.z, a23.w);
            as[4] = make_float2(a45.x, a45.y);
            as[5] = make_float2(a45.z, a45.w);
            as[6] = make_float2(a67.x, a67.y);
            as[7] = make_float2(a67.z, a67.w);
            float4 k0 = *(const float4*)&Ks[buf][li * 512 + jg * 4];
            float4 k1 = *(const float4*)&Ks[buf][li * 512 + 256 + jg * 4];
            float2 kp[4];
            kp[0] = make_float2(k0.x, k0.y);
            kp[1] = make_float2(k0.z, k0.w);
            kp[2] = make_float2(k1.x, k1.y);
            kp[3] = make_float2(k1.z, k1.w);
            #pragma unroll
            for (int nn = 0; nn < 8; nn++)
                #pragma unroll
                for (int qq = 0; qq < 4; qq++)
                    acc[nn][qq] = ffma2(as[nn], kp[qq], acc[nn][qq]);
        }
        __syncthreads();
    }

    #pragma unroll
    for (int nn = 0; nn < 8; nn++) {
        int n = ng * 8 + nn;
        float* mrow = g_M + ((size_t)(lp * 512 + b * NH_ + n)) * D_ + jt * 512;
        float4 o0 = make_float4(acc[nn][0].x, acc[nn][0].y, acc[nn][1].x, acc[nn][1].y);
        float4 o1 = make_float4(acc[nn][2].x, acc[nn][2].y, acc[nn][3].x, acc[nn][3].y);
        *(float4*)(mrow + jg * 4)       = o0;
        *(float4*)(mrow + 256 + jg * 4) = o1;
    }
}

// ---------------------------------------------------------------------------
// Kernel 5a: g_m[b,n,:] = sum over 32 l-split partials
// grid 512 = (b,n), 256 threads (float4 per thread)
// ---------------------------------------------------------------------------
__global__ void k5a_reduce() {
    int bid = blockIdx.x;
    int tid = threadIdx.x;
    float4 s = make_float4(0.f, 0.f, 0.f, 0.f);
    #pragma unroll
    for (int p = 0; p < 32; p++) {
        float4 v = *(const float4*)&g_M[((size_t)(p * 512 + bid)) * D_ + tid * 4];
        s.x += v.x; s.y += v.y; s.z += v.z; s.w += v.w;
    }
    *(float4*)&g_m[(size_t)bid * D_ + tid * 4] = s;
}

// ---------------------------------------------------------------------------
// Kernel 5b: out[b, n*64+row] = Wv[n*64+row,:] . m[b,n,:] + bv
// grid (n=16, bg=4), 256 threads (8 warps x 8 rows, 8 b each). Wv read ONCE.
// ---------------------------------------------------------------------------
__global__ void k5b_out(const float* __restrict__ Wv,
                        const float* __restrict__ bv,
                        float* __restrict__ dout) {
    int n = blockIdx.x, bg = blockIdx.y;
    __shared__ float Ms[8][D_];   // 32 KB
    int tid = threadIdx.x;
    int w = tid >> 5, lane = tid & 31;

    #pragma unroll
    for (int r = 0; r < 8; r++) {
        int f = tid + 256 * r;               // float4 slot 0..2047
        int bb = f >> 8, c = (f & 255) * 4;
        *(float4*)&Ms[bb][c] =
            *(const float4*)&g_m[((size_t)((bg * 8 + bb) * NH_ + n)) * D_ + c];
    }
    __syncthreads();

    for (int rr = 0; rr < 8; rr++) {
        int row = w * 8 + rr;
        int grow = n * DH_ + row;
        const float4* wr = (const float4*)(Wv + (size_t)grow * D_);
        float acc[8];
        #pragma unroll
        for (int bb = 0; bb < 8; bb++) acc[bb] = 0.f;
        #pragma unroll
        for (int it = 0; it < 8; it++) {
            int idx = lane + 32 * it;
            float4 wv = wr[idx];
            #pragma unroll
            for (int bb = 0; bb < 8; bb++) {
                float4 mm = *(const float4*)&Ms[bb][idx * 4];
                acc[bb] += wv.x * mm.x + wv.y * mm.y + wv.z * mm.z + wv.w * mm.w;
            }
        }
        #pragma unroll
        for (int bb = 0; bb < 8; bb++) {
            float v = acc[bb];
            #pragma unroll
            for (int o = 16; o; o >>= 1) v += __shfl_xor_sync(0xFFFFFFFFu, v, o);
            if (lane == bb)
                dout[(size_t)(bg * 8 + bb) * D_ + grow] = v + bv[grow];
        }
    }
}

// ---------------------------------------------------------------------------
extern "C" void kernel_launch(void* const* d_in, const int* in_sizes, int n_in,
                              void* d_out, int out_size) {
    const float* q  = (const float*)d_in[0];
    const float* k  = (const float*)d_in[1];
    const float* Wq = (const float*)d_in[2];
    const float* bq = (const float*)d_in[3];
    const float* Wk = (const float*)d_in[4];
    const float* bk = (const float*)d_in[5];  (void)bk;
    const float* Wv = (const float*)d_in[6];
    const float* bv = (const float*)d_in[7];
    float* out = (float*)d_out;

    k1a_qs    <<<dim3(8, 32), 256>>>(q, Wq, bq);
    k1b_C     <<<dim3(8, 16), 128>>>(Wk);
    k2_scores <<<dim3(4, 8, 32), 128>>>(k);
    k3_softmax<<<512, 256>>>(out);
    k4_weighted<<<dim3(2, 32, 32), 128>>>(k, out);
    k5a_reduce<<<512, 256>>>();
    k5b_out   <<<dim3(16, 4), 256>>>(Wv, bv, out);
}

// round 6
// speedup vs baseline: 1.6732x; 1.0014x over previous
#include <cuda_runtime.h>
#include <cuda_bf16.h>
#include <cstdint>

// Problem constants
#define B_   32
#define L_   2048
#define D_   1024
#define NH_  16
#define DH_  64

// Scratch (device globals; no allocation)
__device__ float g_qs[B_*NH_*DH_];         // 128 KB qs = Wq q + bq
__device__ float g_C [B_*NH_*D_];          // 2 MB   combined query-key vectors (scaled by 1/8)
__device__ float g_S8[8][B_*NH_*L_];       // 32 MB  partial raw scores (8 j-chunks)
__device__ float g_M [32*B_*NH_*D_];       // 64 MB  weighted-k partial sums (32 l-splits)
__device__ float g_m [B_*NH_*D_];          // 2 MB   reduced weighted-k sums

// Packed dual-FMA (Blackwell f32x2 pipe)
__device__ __forceinline__ float2 ffma2(float2 a, float2 b, float2 c) {
    float2 d;
    asm("{\n\t"
        ".reg .b64 ra, rb, rc;\n\t"
        "mov.b64 ra, {%2,%3};\n\t"
        "mov.b64 rb, {%4,%5};\n\t"
        "mov.b64 rc, {%6,%7};\n\t"
        "fma.rn.f32x2 rc, ra, rb, rc;\n\t"
        "mov.b64 {%0,%1}, rc;\n\t"
        "}"
        : "=f"(d.x), "=f"(d.y)
        : "f"(a.x), "f"(a.y), "f"(b.x), "f"(b.y), "f"(c.x), "f"(c.y));
    return d;
}

#define CP_ASYNC16(dst_u32, src_ptr) \
    asm volatile("cp.async.cg.shared.global [%0], [%1], 16;" \
                 :: "r"(dst_u32), "l"(src_ptr) : "memory")
#define CP_COMMIT() asm volatile("cp.async.commit_group;" ::: "memory")

// ---------------------------------------------------------------------------
// Kernel 1a: qs[b, row] = Wq[row,:] . q[b,:] + bq[row]
// ---------------------------------------------------------------------------
__global__ void k1a_qs(const float* __restrict__ q,
                       const float* __restrict__ Wq,
                       const float* __restrict__ bq) {
    int rb = blockIdx.x, b = blockIdx.y;
    __shared__ float4 q4[D_ / 4];
    int tid = threadIdx.x;
    int w = tid >> 5, lane = tid & 31;

    for (int i = tid; i < D_ / 4; i += 256)
        q4[i] = ((const float4*)(q + (size_t)b * D_))[i];
    __syncthreads();

    for (int t = 0; t < 16; t++) {
        int row = rb * 128 + w * 16 + t;
        const float4* wr = (const float4*)(Wq + (size_t)row * D_);
        float p = 0.f;
        #pragma unroll
        for (int it = 0; it < 8; it++) {
            int idx = lane + 32 * it;
            float4 a = wr[idx], qv = q4[idx];
            p += a.x * qv.x + a.y * qv.y + a.z * qv.z + a.w * qv.w;
        }
        #pragma unroll
        for (int o = 16; o; o >>= 1) p += __shfl_xor_sync(0xFFFFFFFFu, p, o);
        if (lane == 0) g_qs[(size_t)b * D_ + row] = p + bq[row];
    }
}

// ---------------------------------------------------------------------------
// Kernel 1b: C[b,n,j] = 0.125 * sum_d qs[b, n*64+d] * Wk[n*64+d, j]
// ---------------------------------------------------------------------------
__global__ void k1b_C(const float* __restrict__ Wk) {
    int jt = blockIdx.x, n = blockIdx.y;
    __shared__ float Ws[DH_ * 128];
    __shared__ float Qs[B_ * DH_];
    int tid = threadIdx.x;

    #pragma unroll
    for (int r = 0; r < 16; r++) {
        int f = tid + 128 * r;
        int b = f >> 6, d = f & 63;
        Qs[b * DH_ + d] = g_qs[(size_t)b * D_ + n * DH_ + d];
    }
    #pragma unroll
    for (int r = 0; r < 64; r++)
        Ws[r * 128 + tid] = Wk[(size_t)(n * DH_ + r) * D_ + jt * 128 + tid];
    __syncthreads();

    float acc[B_];
    #pragma unroll
    for (int b = 0; b < B_; b++) acc[b] = 0.f;
    for (int d = 0; d < DH_; d++) {
        float w = Ws[d * 128 + tid];
        #pragma unroll
        for (int b = 0; b < B_; b++) acc[b] += Qs[b * DH_ + d] * w;
    }
    #pragma unroll
    for (int b = 0; b < B_; b++)
        g_C[(size_t)(b * NH_ + n) * D_ + jt * 128 + tid] = acc[b] * 0.125f;
}

// ---------------------------------------------------------------------------
// Kernel 2 v3: partial scores over a 128-j chunk.
// grid (lt=4, js=8, b=32) = 1024 blocks, 128 threads.
// Register-pipelined double-buffered transpose staging (8-j steps, 16 steps).
// C tile staged ONCE per block (plain floats; splats built in regs).
// Conflict-free transpose STS; conflict-free LDS.128 compute loads.
// ---------------------------------------------------------------------------
__global__ void __launch_bounds__(128) k2_scores(const float* __restrict__ k) {
    int lt = blockIdx.x;            // 0..3  (512-l tile)
    int js = blockIdx.y;            // 0..7  (128-j chunk)
    int b  = blockIdx.z;
    __shared__ float CsT[128 * 16];      // 8 KB  [j][n]
    __shared__ float KsT[2][8 * 516];    // 33 KB [buf][j-in-step][l] pitch 516
    int tid = threadIdx.x;
    int ng = tid >> 6;              // 0..1 -> n base = ng*8
    int lg = tid & 63;              // l sets: lg*4..+4 and 256+lg*4..+4

    float2 acc[8][4];
    #pragma unroll
    for (int nn = 0; nn < 8; nn++)
        #pragma unroll
        for (int lp = 0; lp < 4; lp++) acc[nn][lp] = make_float2(0.f, 0.f);

    const float* kb = k + ((size_t)b * L_ + (size_t)lt * 512) * D_ + js * 128;
    const float* Cb = g_C + (size_t)(b * NH_) * D_ + js * 128;

    // stage C tile once: 128 j x 16 n
    #pragma unroll
    for (int e = 0; e < 16; e++) {
        int f = tid + 128 * e;
        int j = f >> 4, n = f & 15;
        CsT[j * 16 + n] = Cb[(size_t)n * D_ + j];
    }

    // register staging buffer: 8 float4 = one 8-j step (512 l x 8 j)
    float4 rg[8];
    #define K2_LDG(j0)                                                        \
        _Pragma("unroll")                                                     \
        for (int r = 0; r < 8; r++) {                                         \
            int f = tid + 128 * r;                                            \
            int l = f >> 1, h = f & 1;                                        \
            rg[r] = *(const float4*)(kb + (size_t)l * D_ + (j0) + h * 4);     \
        }

    K2_LDG(0);

    for (int c = 0; c < 16; c++) {
        float* buf = &KsT[c & 1][0];
        // transpose STS (conflict-free: bank = (16h + 4i + l) % 32)
        #pragma unroll
        for (int r = 0; r < 8; r++) {
            int f = tid + 128 * r;
            int l = f >> 1, h = f & 1;
            float* d0 = &buf[(h * 4) * 516 + l];
            d0[0 * 516] = rg[r].x;
            d0[1 * 516] = rg[r].y;
            d0[2 * 516] = rg[r].z;
            d0[3 * 516] = rg[r].w;
        }
        __syncthreads();
        if (c < 15) { K2_LDG((c + 1) * 8); }

        #pragma unroll
        for (int ji = 0; ji < 8; ji++) {
            int j = c * 8 + ji;
            // C broadcast loads (same address per warp) + reg splat build
            float4 cA = *(const float4*)&CsT[j * 16 + ng * 8];
            float4 cB = *(const float4*)&CsT[j * 16 + ng * 8 + 4];
            float2 cs[8];
            cs[0] = make_float2(cA.x, cA.x);
            cs[1] = make_float2(cA.y, cA.y);
            cs[2] = make_float2(cA.z, cA.z);
            cs[3] = make_float2(cA.w, cA.w);
            cs[4] = make_float2(cB.x, cB.x);
            cs[5] = make_float2(cB.y, cB.y);
            cs[6] = make_float2(cB.z, cB.z);
            cs[7] = make_float2(cB.w, cB.w);
            float4 kA = *(const float4*)&buf[ji * 516 + lg * 4];
            float4 kB = *(const float4*)&buf[ji * 516 + 256 + lg * 4];
            float2 kp[4];
            kp[0] = make_float2(kA.x, kA.y);
            kp[1] = make_float2(kA.z, kA.w);
            kp[2] = make_float2(kB.x, kB.y);
            kp[3] = make_float2(kB.z, kB.w);
            #pragma unroll
            for (int nn = 0; nn < 8; nn++)
                #pragma unroll
                for (int lp = 0; lp < 4; lp++)
                    acc[nn][lp] = ffma2(cs[nn], kp[lp], acc[nn][lp]);
        }
    }
    #undef K2_LDG

    float* Sp = g_S8[js];
    #pragma unroll
    for (int nn = 0; nn < 8; nn++) {
        int n = ng * 8 + nn;
        float* base = Sp + (size_t)(b * NH_ + n) * L_ + lt * 512;
        float4 o0 = make_float4(acc[nn][0].x, acc[nn][0].y, acc[nn][1].x, acc[nn][1].y);
        float4 o1 = make_float4(acc[nn][2].x, acc[nn][2].y, acc[nn][3].x, acc[nn][3].y);
        *(float4*)(base + lg * 4)       = o0;
        *(float4*)(base + 256 + lg * 4) = o1;
    }
}

// ---------------------------------------------------------------------------
// Kernel 3: sum 8 partials, softmax over l, write attn_flat to d_out
// ---------------------------------------------------------------------------
__global__ void k3_softmax(float* __restrict__ dout) {
    int bid = blockIdx.x;
    int b = bid >> 4, n = bid & 15;
    float* dst = dout + (size_t)B_ * NH_ * DH_ + ((size_t)(n * B_ + b)) * L_;
    __shared__ float red[8];
    int tid = threadIdx.x;
    int w = tid >> 5, lane = tid & 31;

    float v[8];
    float mx = -1e30f;
    #pragma unroll
    for (int e = 0; e < 8; e++) {
        size_t idx = (size_t)bid * L_ + tid + 256 * e;
        float s = 0.f;
        #pragma unroll
        for (int p = 0; p < 8; p++) s += g_S8[p][idx];
        v[e] = s;
        mx = fmaxf(mx, v[e]);
    }
    #pragma unroll
    for (int o = 16; o; o >>= 1) mx = fmaxf(mx, __shfl_xor_sync(0xFFFFFFFFu, mx, o));
    if (lane == 0) red[w] = mx;
    __syncthreads();
    float m_all = red[0];
    #pragma unroll
    for (int i = 1; i < 8; i++) m_all = fmaxf(m_all, red[i]);
    __syncthreads();

    float s = 0.f;
    #pragma unroll
    for (int e = 0; e < 8; e++) {
        v[e] = __expf(v[e] - m_all);
        s += v[e];
    }
    #pragma unroll
    for (int o = 16; o; o >>= 1) s += __shfl_xor_sync(0xFFFFFFFFu, s, o);
    if (lane == 0) red[w] = s;
    __syncthreads();
    float tot = 0.f;
    #pragma unroll
    for (int i = 0; i < 8; i++) tot += red[i];
    float inv = 1.0f / tot;
    #pragma unroll
    for (int e = 0; e < 8; e++) dst[tid + 256 * e] = v[e] * inv;
}

// ---------------------------------------------------------------------------
// Kernel 4: M[lp][b,n,j] = sum_{l in lp (64)} attn[b,n,l] * k[b,l,j]
// grid (jt=2, lp=32, b=32) = 2048 blocks, 128 threads. cp.async pipelined.
// ---------------------------------------------------------------------------
__global__ void __launch_bounds__(128) k4_weighted(const float* __restrict__ k,
                                                   const float* __restrict__ dout) {
    int jt = blockIdx.x;
    int lp = blockIdx.y;
    int b  = blockIdx.z;
    __shared__ float Ks[2][8 * 512];
    __shared__ float2 As2[2][8][16];
    int tid = threadIdx.x;
    int ng = tid >> 6;
    int jg = tid & 63;

    float2 acc[8][4];
    #pragma unroll
    for (int nn = 0; nn < 8; nn++)
        #pragma unroll
        for (int qq = 0; qq < 4; qq++) acc[nn][qq] = make_float2(0.f, 0.f);

    const float* attn = dout + (size_t)B_ * NH_ * DH_;
    const float* kb = k + ((size_t)b * L_) * D_ + jt * 512;
    int lbeg = lp * 64;

    auto stage = [&](int s, int l0) {
        #pragma unroll
        for (int r = 0; r < 8; r++) {
            int f = tid + 128 * r;
            int l = f >> 7, c = (f & 127) * 4;
            uint32_t dst = (uint32_t)__cvta_generic_to_shared(&Ks[s][l * 512 + c]);
            CP_ASYNC16(dst, kb + (size_t)(l0 + l) * D_ + c);
        }
        int l = tid >> 4, nn = tid & 15;
        float a = attn[((size_t)(nn * B_ + b)) * L_ + l0 + l];
        As2[s][l][nn] = make_float2(a, a);
    };

    stage(0, lbeg);
    CP_COMMIT();

    for (int c = 0; c < 8; c++) {
        if (c < 7) {
            stage((c + 1) & 1, lbeg + (c + 1) * 8);
            CP_COMMIT();
            asm volatile("cp.async.wait_group 1;" ::: "memory");
        } else {
            asm volatile("cp.async.wait_group 0;" ::: "memory");
        }
        __syncthreads();

        int buf = c & 1;
        #pragma unroll
        for (int li = 0; li < 8; li++) {
            const float4* ar = (const float4*)&As2[buf][li][ng * 8];
            float4 a01 = ar[0], a23 = ar[1], a45 = ar[2], a67 = ar[3];
            float2 as[8];
            as[0] = make_float2(a01.x, a01.y);
            as[1] = make_float2(a01.z, a01.w);
            as[2] = make_float2(a23.x, a23.y);
            as[3] = make_float2(a23.z, a23.w);
            as[4] = make_float2(a45.x, a45.y);
            as[5] = make_float2(a45.z, a45.w);
            as[6] = make_float2(a67.x, a67.y);
            as[7] = make_float2(a67.z, a67.w);
            float4 k0 = *(const float4*)&Ks[buf][li * 512 + jg * 4];
            float4 k1 = *(const float4*)&Ks[buf][li * 512 + 256 + jg * 4];
            float2 kp[4];
            kp[0] = make_float2(k0.x, k0.y);
            kp[1] = make_float2(k0.z, k0.w);
            kp[2] = make_float2(k1.x, k1.y);
            kp[3] = make_float2(k1.z, k1.w);
            #pragma unroll
            for (int nn = 0; nn < 8; nn++)
                #pragma unroll
                for (int qq = 0; qq < 4; qq++)
                    acc[nn][qq] = ffma2(as[nn], kp[qq], acc[nn][qq]);
        }
        __syncthreads();
    }

    #pragma unroll
    for (int nn = 0; nn < 8; nn++) {
        int n = ng * 8 + nn;
        float* mrow = g_M + ((size_t)(lp * 512 + b * NH_ + n)) * D_ + jt * 512;
        float4 o0 = make_float4(acc[nn][0].x, acc[nn][0].y, acc[nn][1].x, acc[nn][1].y);
        float4 o1 = make_float4(acc[nn][2].x, acc[nn][2].y, acc[nn][3].x, acc[nn][3].y);
        *(float4*)(mrow + jg * 4)       = o0;
        *(float4*)(mrow + 256 + jg * 4) = o1;
    }
}

// ---------------------------------------------------------------------------
// Kernel 5a: g_m[b,n,:] = sum over 32 l-split partials
// ---------------------------------------------------------------------------
__global__ void k5a_reduce() {
    int bid = blockIdx.x;
    int tid = threadIdx.x;
    float4 s = make_float4(0.f, 0.f, 0.f, 0.f);
    #pragma unroll
    for (int p = 0; p < 32; p++) {
        float4 v = *(const float4*)&g_M[((size_t)(p * 512 + bid)) * D_ + tid * 4];
        s.x += v.x; s.y += v.y; s.z += v.z; s.w += v.w;
    }
    *(float4*)&g_m[(size_t)bid * D_ + tid * 4] = s;
}

// ---------------------------------------------------------------------------
// Kernel 5b: out[b, n*64+row] = Wv[n*64+row,:] . m[b,n,:] + bv
// ---------------------------------------------------------------------------
__global__ void k5b_out(const float* __restrict__ Wv,
                        const float* __restrict__ bv,
                        float* __restrict__ dout) {
    int n = blockIdx.x, bg = blockIdx.y;
    __shared__ float Ms[8][D_];
    int tid = threadIdx.x;
    int w = tid >> 5, lane = tid & 31;

    #pragma unroll
    for (int r = 0; r < 8; r++) {
        int f = tid + 256 * r;
        int bb = f >> 8, c = (f & 255) * 4;
        *(float4*)&Ms[bb][c] =
            *(const float4*)&g_m[((size_t)((bg * 8 + bb) * NH_ + n)) * D_ + c];
    }
    __syncthreads();

    for (int rr = 0; rr < 8; rr++) {
        int row = w * 8 + rr;
        int grow = n * DH_ + row;
        const float4* wr = (const float4*)(Wv + (size_t)grow * D_);
        float acc[8];
        #pragma unroll
        for (int bb = 0; bb < 8; bb++) acc[bb] = 0.f;
        #pragma unroll
        for (int it = 0; it < 8; it++) {
            int idx = lane + 32 * it;
            float4 wv = wr[idx];
            #pragma unroll
            for (int bb = 0; bb < 8; bb++) {
                float4 mm = *(const float4*)&Ms[bb][idx * 4];
                acc[bb] += wv.x * mm.x + wv.y * mm.y + wv.z * mm.z + wv.w * mm.w;
            }
        }
        #pragma unroll
        for (int bb = 0; bb < 8; bb++) {
            float v = acc[bb];
            #pragma unroll
            for (int o = 16; o; o >>= 1) v += __shfl_xor_sync(0xFFFFFFFFu, v, o);
            if (lane == bb)
                dout[(size_t)(bg * 8 + bb) * D_ + grow] = v + bv[grow];
        }
    }
}

// ---------------------------------------------------------------------------
extern "C" void kernel_launch(void* const* d_in, const int* in_sizes, int n_in,
                              void* d_out, int out_size) {
    const float* q  = (const float*)d_in[0];
    const float* k  = (const float*)d_in[1];
    const float* Wq = (const float*)d_in[2];
    const float* bq = (const float*)d_in[3];
    const float* Wk = (const float*)d_in[4];
    const float* bk = (const float*)d_in[5];  (void)bk;
    const float* Wv = (const float*)d_in[6];
    const float* bv = (const float*)d_in[7];
    float* out = (float*)d_out;

    k1a_qs    <<<dim3(8, 32), 256>>>(q, Wq, bq);
    k1b_C     <<<dim3(8, 16), 128>>>(Wk);
    k2_scores <<<dim3(4, 8, 32), 128>>>(k);
    k3_softmax<<<512, 256>>>(out);
    k4_weighted<<<dim3(2, 32, 32), 128>>>(k, out);
    k5a_reduce<<<512, 256>>>();
    k5b_out   <<<dim3(16, 4), 256>>>(Wv, bv, out);
}